// round 15
// baseline (speedup 1.0000x reference)
#include <cuda_runtime.h>
#include <cuda_bf16.h>
#include <math.h>
#include <cstdint>

#define Nn 50000
#define Ee 1600000
#define NLO 40000
#define NHI 10000

// ---------------------------------------------------------------------------
// Scratch (static device arrays)
// ---------------------------------------------------------------------------
__device__ float g_h[2][256];           // impulse responses lo/hi
// Folded W1, split bf16, packed per 16-k segment as LDS.128-ready quads:
// word index within combo = ksg*1024 + nt*128 + lane*4 + slot
// slot: 0=h0(r=0) 1=h1(r=1) 2=l0 3=l1 ; bf16 halfword p = kr&1
__device__ uint32_t g_wtf[4][16384];
__device__ float g_wsrc[Nn];
__device__ float g_wdst[Nn];
__device__ double g_part[2048];
__device__ unsigned g_cnt = 0;

// ---------------------------------------------------------------------------
// cp.async + PDL helpers
// ---------------------------------------------------------------------------
__device__ __forceinline__ void cpa16(void* dst_smem, const void* src_gmem) {
    unsigned d = (unsigned)__cvta_generic_to_shared(dst_smem);
    asm volatile("cp.async.cg.shared.global [%0], [%1], 16;" :: "r"(d), "l"(src_gmem));
}
__device__ __forceinline__ void cpa_commit() { asm volatile("cp.async.commit_group;"); }
template<int NW> __device__ __forceinline__ void cpa_wait() {
    asm volatile("cp.async.wait_group %0;" :: "n"(NW));
}
__device__ __forceinline__ void pdl_trigger() {
    asm volatile("griddepcontrol.launch_dependents;");
}
__device__ __forceinline__ void pdl_wait() {
    asm volatile("griddepcontrol.wait;" ::: "memory");
}

// ---------------------------------------------------------------------------
// bf16 mma.sync m16n8k16
// ---------------------------------------------------------------------------
__device__ __forceinline__ void mma16816(float* c, const uint32_t* a,
                                         uint32_t b0, uint32_t b1) {
    asm volatile(
        "mma.sync.aligned.m16n8k16.row.col.f32.bf16.bf16.f32 "
        "{%0,%1,%2,%3}, {%4,%5,%6,%7}, {%8,%9}, {%0,%1,%2,%3};"
        : "+f"(c[0]), "+f"(c[1]), "+f"(c[2]), "+f"(c[3])
        : "r"(a[0]), "r"(a[1]), "r"(a[2]), "r"(a[3]), "r"(b0), "r"(b1));
}

// ---------------------------------------------------------------------------
// K0: impulse responses
// ---------------------------------------------------------------------------
__global__ void k_imp(const float* __restrict__ bhi, const float* __restrict__ ahi,
                      const float* __restrict__ blo, const float* __restrict__ alo)
{
    int f = threadIdx.x;
    if (f >= 2) return;
    const float* bc = f ? bhi : blo;
    const float* ac = f ? ahi : alo;
    float inv = 1.0f / ac[0];
    float b0 = bc[0]*inv, b1 = bc[1]*inv, b2 = bc[2]*inv,
          b3 = bc[3]*inv, b4 = bc[4]*inv, b5 = bc[5]*inv;
    float a1 = ac[1]*inv, a2 = ac[2]*inv, a3 = ac[3]*inv,
          a4 = ac[4]*inv, a5 = ac[5]*inv;
    float z0=0.f, z1=0.f, z2=0.f, z3=0.f, z4=0.f;
    for (int d = 0; d < 256; d++) {
        float xv = (d == 0) ? 1.0f : 0.0f;
        float y  = fmaf(b0, xv, z0);
        z0 = fmaf(-a1, y, fmaf(b1, xv, z1));
        z1 = fmaf(-a2, y, fmaf(b2, xv, z2));
        z2 = fmaf(-a3, y, fmaf(b3, xv, z3));
        z3 = fmaf(-a4, y, fmaf(b4, xv, z4));
        z4 = fmaf(-a5, y, b5 * xv);
        g_h[f][d] = y;
    }
}

// ---------------------------------------------------------------------------
// K1: fold IIR into W1, split bf16, LDS.128-ready fragment quads.
//   wt(combo,k,n) = sum_{d>=k} h_f[d-k] * W1_br[d][n]
// ---------------------------------------------------------------------------
__global__ void __launch_bounds__(256) k_fold(
    const float* __restrict__ w1s, const float* __restrict__ w1d)
{
    __shared__ float hs[256];
    pdl_trigger();                  // let k_gemm start its A-gather prologue
    int combo = blockIdx.y;
    int f  = combo & 1;
    int br = combo >> 1;
    int t  = threadIdx.x;
    int k  = blockIdx.x * 4 + (t >> 6);
    int n  = t & 63;
    for (int d = t; d < 256; d += 256) hs[d] = g_h[f][d];
    __syncthreads();

    const float* W1 = br ? w1d : w1s;
    float acc = 0.f;
    for (int d = k; d < 256; d++)
        acc = fmaf(hs[d - k], __ldg(W1 + d*64 + n), acc);

    __nv_bfloat16 hi = __float2bfloat16(acc);
    __nv_bfloat16 lo = __float2bfloat16(acc - __bfloat162float(hi));

    int ks = k >> 4, kr = k & 15;
    int r  = kr >> 3, p = kr & 1;
    int lane = (n & 7) * 4 + ((kr & 7) >> 1);
    int nt = n >> 3;
    uint32_t base32 = (uint32_t)(ks*1024 + nt*128 + lane*4);
    __nv_bfloat16* w = (__nv_bfloat16*)(g_wtf[combo] + base32);
    w[r*2 + p]       = hi;   // slot r   (h0/h1)
    w[(2+r)*2 + p]   = lo;   // slot 2+r (l0/l1)
}

// ---------------------------------------------------------------------------
// K2: gathered split-bf16 HMMA GEMM + fused relu/w2 epilogue.
// R11 steady state (3-buffer ring, KC=16, wait<2>); PDL prologue splits
// A-staging (pre-dependency, overlaps k_fold) from W-staging (post-wait).
// Group map: A0=G0, A1=G1, W0=G2, W1=G3, chunk c>=2 joint = G_{2+c}.
// ---------------------------------------------------------------------------
#define NB_LO 313
#define NB_HI 79
#define NB_BR 392
#define KC 16
#define NCH 16
#define A_LD 20

__global__ void __launch_bounds__(256) k_gemm(
    const float* __restrict__ x,
    const float* __restrict__ b1s, const float* __restrict__ b1d,
    const float* __restrict__ w2s, const float* __restrict__ w2d,
    const float* __restrict__ b2s, const float* __restrict__ b2d,
    const int* __restrict__ isl, const int* __restrict__ ish,
    const int* __restrict__ idl, const int* __restrict__ idh)
{
    __shared__ float As[3][128 * A_LD];
    __shared__ uint32_t Wsm[3][1024];
    __shared__ int nids[128];

    pdl_trigger();                  // let k_edge start its streaming prologue

    int t = threadIdx.x;
    int warp = t >> 5, lane = t & 31;

    int bx = blockIdx.x;
    int br = bx / NB_BR;
    int r  = bx - br * NB_BR;
    int f, pos0, lim;
    if (r < NB_LO) { f = 0; pos0 = r * 128;            lim = NLO; }
    else           { f = 1; pos0 = (r - NB_LO) * 128;  lim = NHI; }
    int combo = br * 2 + f;
    const int* idx = f ? (br ? idh : ish) : (br ? idl : isl);
    const uint32_t* wsrc = g_wtf[combo];

    if (t < 128) {
        int p = pos0 + t;
        nids[t] = (p < lim) ? __ldg(idx + p) : 0;
    }
    __syncthreads();

    float acc[8][4];
#pragma unroll
    for (int nt = 0; nt < 8; nt++)
#pragma unroll
        for (int q = 0; q < 4; q++) acc[nt][q] = 0.f;

#define STAGE_A(c) do { int _b = (c) % 3; int _kc = (c) * KC;                 \
        _Pragma("unroll")                                                     \
        for (int q = 0; q < 2; q++) {                                         \
            int u = t + 256*q; int row = u >> 2, seg = u & 3;                 \
            cpa16(&As[_b][row * A_LD + seg * 4],                              \
                  x + (size_t)nids[row] * 256 + _kc + seg * 4);               \
        }                                                                     \
        cpa_commit(); } while (0)
#define STAGE_W(c) do { int _b = (c) % 3;                                     \
        cpa16(&Wsm[_b][t * 4], wsrc + (c) * 1024 + t * 4);                    \
        cpa_commit(); } while (0)
#define STAGE_AW(c) do { int _b = (c) % 3; int _kc = (c) * KC;                \
        _Pragma("unroll")                                                     \
        for (int q = 0; q < 2; q++) {                                         \
            int u = t + 256*q; int row = u >> 2, seg = u & 3;                 \
            cpa16(&As[_b][row * A_LD + seg * 4],                              \
                  x + (size_t)nids[row] * 256 + _kc + seg * 4);               \
        }                                                                     \
        cpa16(&Wsm[_b][t * 4], wsrc + (c) * 1024 + t * 4);                    \
        cpa_commit(); } while (0)

    // Pre-dependency: A gathers for chunks 0,1 (inputs only)
    STAGE_A(0);        // G0
    STAGE_A(1);        // G1
    pdl_wait();        // k_fold grid complete -> g_wtf visible
    STAGE_W(0);        // G2
    STAGE_W(1);        // G3

#pragma unroll 1
    for (int c = 0; c < NCH; c++) {
        if (c + 2 < NCH)      { STAGE_AW(c + 2); cpa_wait<2>(); }
        else if (c + 1 < NCH) { cpa_wait<1>(); }
        else                  { cpa_wait<0>(); }
        __syncthreads();

        int buf = c % 3;
        const float* Ab = &As[buf][(warp * 16) * A_LD];
        int rrow = lane >> 2;
        int kp   = (lane & 3) * 2;

        float2 f0 = *(const float2*)(Ab + rrow * A_LD + kp);
        float2 f1 = *(const float2*)(Ab + (rrow + 8) * A_LD + kp);
        float2 f2 = *(const float2*)(Ab + rrow * A_LD + kp + 8);
        float2 f3 = *(const float2*)(Ab + (rrow + 8) * A_LD + kp + 8);

        uint32_t ahi[4], alo[4];
        float2 fs[4] = {f0, f1, f2, f3};
#pragma unroll
        for (int i = 0; i < 4; i++) {
            __nv_bfloat162 hp;
            hp.x = __float2bfloat16(fs[i].x);
            hp.y = __float2bfloat16(fs[i].y);
            __nv_bfloat162 lp;
            lp.x = __float2bfloat16(fs[i].x - __bfloat162float(hp.x));
            lp.y = __float2bfloat16(fs[i].y - __bfloat162float(hp.y));
            ahi[i] = *(uint32_t*)&hp;
            alo[i] = *(uint32_t*)&lp;
        }

        const uint4* Wb = (const uint4*)Wsm[buf] + lane;
#pragma unroll
        for (int nt = 0; nt < 8; nt++) {
            uint4 wv = Wb[nt * 32];     // {h0, h1, l0, l1}
            mma16816(acc[nt], ahi, wv.x, wv.y);
            mma16816(acc[nt], ahi, wv.z, wv.w);
            mma16816(acc[nt], alo, wv.x, wv.y);
        }
        __syncthreads();
    }
#undef STAGE_A
#undef STAGE_W
#undef STAGE_AW

    const float* b1p = br ? b1d : b1s;
    const float* w2p = br ? w2d : w2s;
    float pA = 0.f, pB = 0.f;
#pragma unroll
    for (int nt = 0; nt < 8; nt++) {
        int n0 = nt * 8 + (lane & 3) * 2;
        float ba = __ldg(b1p + n0),     bb = __ldg(b1p + n0 + 1);
        float wa = __ldg(w2p + n0),     wb = __ldg(w2p + n0 + 1);
        pA += fmaxf(acc[nt][0] + ba, 0.f) * wa + fmaxf(acc[nt][1] + bb, 0.f) * wb;
        pB += fmaxf(acc[nt][2] + ba, 0.f) * wa + fmaxf(acc[nt][3] + bb, 0.f) * wb;
    }
    pA += __shfl_xor_sync(0xffffffffu, pA, 1);
    pA += __shfl_xor_sync(0xffffffffu, pA, 2);
    pB += __shfl_xor_sync(0xffffffffu, pB, 1);
    pB += __shfl_xor_sync(0xffffffffu, pB, 2);
    if ((lane & 3) == 0) {
        float b2v = __ldg(br ? b2d : b2s);
        float* outw = br ? g_wdst : g_wsrc;
        int base = f ? NLO : 0;
        int rowA = pos0 + warp * 16 + (lane >> 2);
        if (rowA < lim)     outw[base + rowA]     = pA + b2v;
        if (rowA + 8 < lim) outw[base + rowA + 8] = pB + b2v;
    }
}

// ---------------------------------------------------------------------------
// K3: edge gate. PDL: stream src/dst/u into smem via cp.async.cg (L2-only,
// keeps L1 for the w gathers) BEFORE the dependency wait; gather after.
// sigmoid((logit(eps)+w)/0.5) = 1 / (1 + ((1-eps)/eps)^2 * exp(-2w))
// ---------------------------------------------------------------------------
#define EPB 2048
#define NPART 782

__global__ void __launch_bounds__(256) k_edge(
    const int* __restrict__ src, const int* __restrict__ dst,
    const float* __restrict__ u, float* __restrict__ out)
{
    __shared__ int   sS[EPB];
    __shared__ int   sD[EPB];
    __shared__ float sU[EPB];
    __shared__ double red[256];
    __shared__ int isLast;

    int t = threadIdx.x;
    int blk0 = blockIdx.x * EPB;

    // Pre-dependency: stage this block's edge slabs (inputs only)
    for (int j = t; j < EPB / 4; j += 256) {
        int g = blk0 + j * 4;
        if (g < Ee) {               // Ee % 4 == 0 -> full vectors only
            cpa16(&sS[j * 4], src + g);
            cpa16(&sD[j * 4], dst + g);
            cpa16(&sU[j * 4], u + g);
        }
    }
    cpa_commit();
    pdl_wait();                     // k_gemm complete -> g_wsrc/g_wdst visible
    cpa_wait<0>();
    __syncthreads();

    float local = 0.0f;
#pragma unroll
    for (int qq = 0; qq < 2; qq++) {
        int i = qq * 1024 + t * 4;
        int g = blk0 + i;
        if (g < Ee) {
            int4   s4 = *(const int4*)&sS[i];
            int4   d4 = *(const int4*)&sD[i];
            float4 u4 = *(const float4*)&sU[i];
            float wv[4] = { __ldg(&g_wsrc[s4.x]) + __ldg(&g_wdst[d4.x]),
                            __ldg(&g_wsrc[s4.y]) + __ldg(&g_wdst[d4.y]),
                            __ldg(&g_wsrc[s4.z]) + __ldg(&g_wdst[d4.z]),
                            __ldg(&g_wsrc[s4.w]) + __ldg(&g_wdst[d4.w]) };
            float uu[4] = { u4.x, u4.y, u4.z, u4.w };
#pragma unroll
            for (int q = 0; q < 4; q++) {
                float eps  = 0.9999f - 0.9998f * uu[q];
                float onem = 0.0001f + 0.9998f * uu[q];
                float rr   = __fdividef(onem, eps);
                float ge   = __expf(-2.0f * wv[q]);
                float aug  = __fdividef(1.0f, fmaf(rr * rr, ge, 1.0f));
                out[1 + g + q] = aug;
                local += aug;
            }
        }
    }

    red[t] = (double)local;
    __syncthreads();
    for (int off = 128; off; off >>= 1) {
        if (t < off) red[t] += red[t + off];
        __syncthreads();
    }
    if (t == 0) {
        g_part[blockIdx.x] = red[0];
        __threadfence();
        unsigned old = atomicAdd(&g_cnt, 1u);
        isLast = (old == NPART - 1);
    }
    __syncthreads();
    if (isLast) {
        double l2 = 0.0;
        for (int i = t; i < NPART; i += 256) l2 += g_part[i];
        red[t] = l2;
        __syncthreads();
        for (int off = 128; off; off >>= 1) {
            if (t < off) red[t] += red[t + off];
            __syncthreads();
        }
        if (t == 0) {
            out[0] = (float)(1.0 - red[0] / (double)Ee);
            g_cnt = 0;
        }
    }
}

// ---------------------------------------------------------------------------
extern "C" void kernel_launch(void* const* d_in, const int* in_sizes, int n_in,
                              void* d_out, int out_size)
{
    const float* node_emb = (const float*)d_in[0];
    const float* w1_src   = (const float*)d_in[1];
    const float* b1_src   = (const float*)d_in[2];
    const float* w2_src   = (const float*)d_in[3];
    const float* b2_src   = (const float*)d_in[4];
    const float* w1_dst   = (const float*)d_in[5];
    const float* b1_dst   = (const float*)d_in[6];
    const float* w2_dst   = (const float*)d_in[7];
    const float* b2_dst   = (const float*)d_in[8];
    const float* b_hi     = (const float*)d_in[9];
    const float* a_hi     = (const float*)d_in[10];
    const float* b_lo     = (const float*)d_in[11];
    const float* a_lo     = (const float*)d_in[12];
    const float* u_eps    = (const float*)d_in[13];
    const int*   src      = (const int*)d_in[14];
    const int*   dst      = (const int*)d_in[15];
    const int*   idx_src_hi = (const int*)d_in[16];
    const int*   idx_src_lo = (const int*)d_in[17];
    const int*   idx_dst_hi = (const int*)d_in[18];
    const int*   idx_dst_lo = (const int*)d_in[19];
    float* out = (float*)d_out;

    k_imp<<<1, 32>>>(b_hi, a_hi, b_lo, a_lo);
    dim3 gfold(64, 4);
    k_fold<<<gfold, 256>>>(w1_src, w1_dst);

    // k_gemm with programmatic dependency on k_fold
    {
        cudaLaunchConfig_t cfg = {};
        cfg.gridDim  = dim3(2 * NB_BR, 1, 1);
        cfg.blockDim = dim3(256, 1, 1);
        cfg.stream   = 0;
        cudaLaunchAttribute at[1];
        at[0].id = cudaLaunchAttributeProgrammaticStreamSerialization;
        at[0].val.programmaticStreamSerializationAllowed = 1;
        cfg.attrs = at;
        cfg.numAttrs = 1;
        cudaLaunchKernelEx(&cfg, k_gemm, node_emb, b1_src, b1_dst,
                           w2_src, w2_dst, b2_src, b2_dst,
                           idx_src_lo, idx_src_hi, idx_dst_lo, idx_dst_hi);
    }
    // k_edge with programmatic dependency on k_gemm
    {
        cudaLaunchConfig_t cfg = {};
        cfg.gridDim  = dim3(NPART, 1, 1);
        cfg.blockDim = dim3(256, 1, 1);
        cfg.stream   = 0;
        cudaLaunchAttribute at[1];
        at[0].id = cudaLaunchAttributeProgrammaticStreamSerialization;
        at[0].val.programmaticStreamSerializationAllowed = 1;
        cfg.attrs = at;
        cfg.numAttrs = 1;
        cudaLaunchKernelEx(&cfg, k_edge, src, dst, u_eps, out);
    }
}

// round 17
// speedup vs baseline: 1.2717x; 1.2717x over previous
#include <cuda_runtime.h>
#include <cuda_bf16.h>
#include <math.h>
#include <cstdint>

#define Nn 50000
#define Ee 1600000
#define NLO 40000
#define NHI 10000

// ---------------------------------------------------------------------------
// Scratch (static device arrays)
// ---------------------------------------------------------------------------
__device__ float g_h[2][256];           // impulse responses lo/hi
// Folded W1, split bf16, packed per 16-k segment as LDS.128-ready quads:
// word index within combo = ksg*1024 + nt*128 + lane*4 + slot
// slot: 0=h0(r=0) 1=h1(r=1) 2=l0 3=l1 ; bf16 halfword p = kr&1
__device__ uint32_t g_wtf[4][16384];
__device__ float g_wsrc[Nn];
__device__ float g_wdst[Nn];
__device__ double g_part[2048];
__device__ unsigned g_cnt = 0;

// ---------------------------------------------------------------------------
// cp.async helpers
// ---------------------------------------------------------------------------
__device__ __forceinline__ void cpa16(void* dst_smem, const void* src_gmem) {
    unsigned d = (unsigned)__cvta_generic_to_shared(dst_smem);
    asm volatile("cp.async.cg.shared.global [%0], [%1], 16;" :: "r"(d), "l"(src_gmem));
}
__device__ __forceinline__ void cpa_commit() { asm volatile("cp.async.commit_group;"); }
template<int NW> __device__ __forceinline__ void cpa_wait() {
    asm volatile("cp.async.wait_group %0;" :: "n"(NW));
}

// ---------------------------------------------------------------------------
// bf16 mma.sync m16n8k16
// ---------------------------------------------------------------------------
__device__ __forceinline__ void mma16816(float* c, const uint32_t* a,
                                         uint32_t b0, uint32_t b1) {
    asm volatile(
        "mma.sync.aligned.m16n8k16.row.col.f32.bf16.bf16.f32 "
        "{%0,%1,%2,%3}, {%4,%5,%6,%7}, {%8,%9}, {%0,%1,%2,%3};"
        : "+f"(c[0]), "+f"(c[1]), "+f"(c[2]), "+f"(c[3])
        : "r"(a[0]), "r"(a[1]), "r"(a[2]), "r"(a[3]), "r"(b0), "r"(b1));
}

// ---------------------------------------------------------------------------
// K0: impulse responses
// ---------------------------------------------------------------------------
__global__ void k_imp(const float* __restrict__ bhi, const float* __restrict__ ahi,
                      const float* __restrict__ blo, const float* __restrict__ alo)
{
    int f = threadIdx.x;
    if (f >= 2) return;
    const float* bc = f ? bhi : blo;
    const float* ac = f ? ahi : alo;
    float inv = 1.0f / ac[0];
    float b0 = bc[0]*inv, b1 = bc[1]*inv, b2 = bc[2]*inv,
          b3 = bc[3]*inv, b4 = bc[4]*inv, b5 = bc[5]*inv;
    float a1 = ac[1]*inv, a2 = ac[2]*inv, a3 = ac[3]*inv,
          a4 = ac[4]*inv, a5 = ac[5]*inv;
    float z0=0.f, z1=0.f, z2=0.f, z3=0.f, z4=0.f;
    for (int d = 0; d < 256; d++) {
        float xv = (d == 0) ? 1.0f : 0.0f;
        float y  = fmaf(b0, xv, z0);
        z0 = fmaf(-a1, y, fmaf(b1, xv, z1));
        z1 = fmaf(-a2, y, fmaf(b2, xv, z2));
        z2 = fmaf(-a3, y, fmaf(b3, xv, z3));
        z3 = fmaf(-a4, y, fmaf(b4, xv, z4));
        z4 = fmaf(-a5, y, b5 * xv);
        g_h[f][d] = y;
    }
}

// ---------------------------------------------------------------------------
// K1: fold IIR into W1, split bf16, LDS.128-ready fragment quads.
//   wt(combo,k,n) = sum_{d>=k} h_f[d-k] * W1_br[d][n]
// grid (64, 4 combos), block 256: k = bx*4 + t/64, n = t%64
// ---------------------------------------------------------------------------
__global__ void __launch_bounds__(256) k_fold(
    const float* __restrict__ w1s, const float* __restrict__ w1d)
{
    __shared__ float hs[256];
    int combo = blockIdx.y;
    int f  = combo & 1;
    int br = combo >> 1;
    int t  = threadIdx.x;
    int k  = blockIdx.x * 4 + (t >> 6);
    int n  = t & 63;
    for (int d = t; d < 256; d += 256) hs[d] = g_h[f][d];
    __syncthreads();

    const float* W1 = br ? w1d : w1s;
    float acc = 0.f;
    for (int d = k; d < 256; d++)
        acc = fmaf(hs[d - k], __ldg(W1 + d*64 + n), acc);

    __nv_bfloat16 hi = __float2bfloat16(acc);
    __nv_bfloat16 lo = __float2bfloat16(acc - __bfloat162float(hi));

    int ks = k >> 4, kr = k & 15;
    int r  = kr >> 3, p = kr & 1;
    int lane = (n & 7) * 4 + ((kr & 7) >> 1);
    int nt = n >> 3;
    uint32_t base32 = (uint32_t)(ks*1024 + nt*128 + lane*4);
    __nv_bfloat16* w = (__nv_bfloat16*)(g_wtf[combo] + base32);
    w[r*2 + p]       = hi;   // slot r   (h0/h1)
    w[(2+r)*2 + p]   = lo;   // slot 2+r (l0/l1)
}

// ---------------------------------------------------------------------------
// K2: gathered split-bf16 HMMA GEMM + fused relu/w2 epilogue.
// 256 threads / 8 warps; tile 128 gathered rows x 64 cols; K=256, KC=16,
// 3-stage cp.async ring. (Measured-best configuration — HMMA-rate floor.)
// ---------------------------------------------------------------------------
#define NB_LO 313
#define NB_HI 79
#define NB_BR 392
#define KC 16
#define NCH 16
#define A_LD 20   // 80B row stride, 16B-aligned

__global__ void __launch_bounds__(256) k_gemm(
    const float* __restrict__ x,
    const float* __restrict__ b1s, const float* __restrict__ b1d,
    const float* __restrict__ w2s, const float* __restrict__ w2d,
    const float* __restrict__ b2s, const float* __restrict__ b2d,
    const int* __restrict__ isl, const int* __restrict__ ish,
    const int* __restrict__ idl, const int* __restrict__ idh)
{
    __shared__ float As[3][128 * A_LD];     // 30720 B
    __shared__ uint32_t Wsm[3][1024];       // 12288 B
    __shared__ int nids[128];

    int t = threadIdx.x;
    int warp = t >> 5, lane = t & 31;

    int bx = blockIdx.x;
    int br = bx / NB_BR;
    int r  = bx - br * NB_BR;
    int f, pos0, lim;
    if (r < NB_LO) { f = 0; pos0 = r * 128;            lim = NLO; }
    else           { f = 1; pos0 = (r - NB_LO) * 128;  lim = NHI; }
    int combo = br * 2 + f;
    const int* idx = f ? (br ? idh : ish) : (br ? idl : isl);
    const uint32_t* wsrc = g_wtf[combo];

    if (t < 128) {
        int p = pos0 + t;
        nids[t] = (p < lim) ? __ldg(idx + p) : 0;
    }
    __syncthreads();

    float acc[8][4];
#pragma unroll
    for (int nt = 0; nt < 8; nt++)
#pragma unroll
        for (int q = 0; q < 4; q++) acc[nt][q] = 0.f;

#define STAGE(c) do { int _b = (c) % 3; int _kc = (c) * KC;                   \
        _Pragma("unroll")                                                     \
        for (int q = 0; q < 2; q++) {                                         \
            int u = t + 256*q; int row = u >> 2, seg = u & 3;                 \
            cpa16(&As[_b][row * A_LD + seg * 4],                              \
                  x + (size_t)nids[row] * 256 + _kc + seg * 4);               \
        }                                                                     \
        cpa16(&Wsm[_b][t * 4], wsrc + (c) * 1024 + t * 4);                    \
        cpa_commit(); } while (0)

    STAGE(0);
    STAGE(1);

#pragma unroll 1
    for (int c = 0; c < NCH; c++) {
        if (c + 2 < NCH)      { STAGE(c + 2); cpa_wait<2>(); }
        else if (c + 1 < NCH) { cpa_wait<1>(); }
        else                  { cpa_wait<0>(); }
        __syncthreads();

        int buf = c % 3;
        const float* Ab = &As[buf][(warp * 16) * A_LD];
        int rrow = lane >> 2;
        int kp   = (lane & 3) * 2;

        float2 f0 = *(const float2*)(Ab + rrow * A_LD + kp);
        float2 f1 = *(const float2*)(Ab + (rrow + 8) * A_LD + kp);
        float2 f2 = *(const float2*)(Ab + rrow * A_LD + kp + 8);
        float2 f3 = *(const float2*)(Ab + (rrow + 8) * A_LD + kp + 8);

        uint32_t ahi[4], alo[4];
        float2 fs[4] = {f0, f1, f2, f3};
#pragma unroll
        for (int i = 0; i < 4; i++) {
            __nv_bfloat162 hp;
            hp.x = __float2bfloat16(fs[i].x);
            hp.y = __float2bfloat16(fs[i].y);
            __nv_bfloat162 lp;
            lp.x = __float2bfloat16(fs[i].x - __bfloat162float(hp.x));
            lp.y = __float2bfloat16(fs[i].y - __bfloat162float(hp.y));
            ahi[i] = *(uint32_t*)&hp;
            alo[i] = *(uint32_t*)&lp;
        }

        const uint4* Wb = (const uint4*)Wsm[buf] + lane;
#pragma unroll
        for (int nt = 0; nt < 8; nt++) {
            uint4 wv = Wb[nt * 32];     // {h0, h1, l0, l1}
            mma16816(acc[nt], ahi, wv.x, wv.y);
            mma16816(acc[nt], ahi, wv.z, wv.w);
            mma16816(acc[nt], alo, wv.x, wv.y);
        }
        __syncthreads();
    }
#undef STAGE

    const float* b1p = br ? b1d : b1s;
    const float* w2p = br ? w2d : w2s;
    float pA = 0.f, pB = 0.f;
#pragma unroll
    for (int nt = 0; nt < 8; nt++) {
        int n0 = nt * 8 + (lane & 3) * 2;
        float ba = __ldg(b1p + n0),     bb = __ldg(b1p + n0 + 1);
        float wa = __ldg(w2p + n0),     wb = __ldg(w2p + n0 + 1);
        pA += fmaxf(acc[nt][0] + ba, 0.f) * wa + fmaxf(acc[nt][1] + bb, 0.f) * wb;
        pB += fmaxf(acc[nt][2] + ba, 0.f) * wa + fmaxf(acc[nt][3] + bb, 0.f) * wb;
    }
    pA += __shfl_xor_sync(0xffffffffu, pA, 1);
    pA += __shfl_xor_sync(0xffffffffu, pA, 2);
    pB += __shfl_xor_sync(0xffffffffu, pB, 1);
    pB += __shfl_xor_sync(0xffffffffu, pB, 2);
    if ((lane & 3) == 0) {
        float b2v = __ldg(br ? b2d : b2s);
        float* outw = br ? g_wdst : g_wsrc;
        int base = f ? NLO : 0;
        int rowA = pos0 + warp * 16 + (lane >> 2);
        if (rowA < lim)     outw[base + rowA]     = pA + b2v;
        if (rowA + 8 < lim) outw[base + rowA + 8] = pB + b2v;
    }
}

// ---------------------------------------------------------------------------
// K3: edge gate, 16 edges/thread, streaming cache hints:
// src/dst/u via __ldcs (evict-first, 16B-aligned vectors), aug via SCALAR
// __stcs (out+1 offset is only 4B-aligned — float4 stores trap). The w
// gathers keep the default caching path so g_wsrc/g_wdst stay L1-hot.
// sigmoid((logit(eps)+w)/0.5) = 1 / (1 + ((1-eps)/eps)^2 * exp(-2w))
// ---------------------------------------------------------------------------
#define EDGES_PER_BLOCK 4096
#define NPART 391

__device__ __forceinline__ float edge_quad(
    const int* __restrict__ src, const int* __restrict__ dst,
    const float* __restrict__ u, float* __restrict__ out, int base)
{
    int4   s4 = __ldcs((const int4*)(src + base));
    int4   d4 = __ldcs((const int4*)(dst + base));
    float4 u4 = __ldcs((const float4*)(u + base));
    float wv[4] = { __ldg(&g_wsrc[s4.x]) + __ldg(&g_wdst[d4.x]),
                    __ldg(&g_wsrc[s4.y]) + __ldg(&g_wdst[d4.y]),
                    __ldg(&g_wsrc[s4.z]) + __ldg(&g_wdst[d4.z]),
                    __ldg(&g_wsrc[s4.w]) + __ldg(&g_wdst[d4.w]) };
    float uu[4] = { u4.x, u4.y, u4.z, u4.w };
    float local = 0.0f;
#pragma unroll
    for (int q = 0; q < 4; q++) {
        float eps  = 0.9999f - 0.9998f * uu[q];
        float onem = 0.0001f + 0.9998f * uu[q];
        float rr   = __fdividef(onem, eps);
        float ge   = __expf(-2.0f * wv[q]);
        float aug  = __fdividef(1.0f, fmaf(rr * rr, ge, 1.0f));
        __stcs(out + 1 + base + q, aug);   // scalar: 4B-aligned target
        local += aug;
    }
    return local;
}

__global__ void __launch_bounds__(256) k_edge(
    const int* __restrict__ src, const int* __restrict__ dst,
    const float* __restrict__ u, float* __restrict__ out)
{
    __shared__ double red[256];
    __shared__ int isLast;
    int t = threadIdx.x;
    int blk0 = blockIdx.x * EDGES_PER_BLOCK;
    float local = 0.0f;
#pragma unroll
    for (int qq = 0; qq < 4; qq++) {
        int b = blk0 + qq * 1024 + t * 4;
        if (b < Ee) local += edge_quad(src, dst, u, out, b);
    }

    red[t] = (double)local;
    __syncthreads();
    for (int off = 128; off; off >>= 1) {
        if (t < off) red[t] += red[t + off];
        __syncthreads();
    }
    if (t == 0) {
        g_part[blockIdx.x] = red[0];
        __threadfence();
        unsigned old = atomicAdd(&g_cnt, 1u);
        isLast = (old == NPART - 1);
    }
    __syncthreads();
    if (isLast) {
        double l2 = 0.0;
        for (int i = t; i < NPART; i += 256) l2 += g_part[i];
        red[t] = l2;
        __syncthreads();
        for (int off = 128; off; off >>= 1) {
            if (t < off) red[t] += red[t + off];
            __syncthreads();
        }
        if (t == 0) {
            out[0] = (float)(1.0 - red[0] / (double)Ee);
            g_cnt = 0;
        }
    }
}

// ---------------------------------------------------------------------------
extern "C" void kernel_launch(void* const* d_in, const int* in_sizes, int n_in,
                              void* d_out, int out_size)
{
    const float* node_emb = (const float*)d_in[0];
    const float* w1_src   = (const float*)d_in[1];
    const float* b1_src   = (const float*)d_in[2];
    const float* w2_src   = (const float*)d_in[3];
    const float* b2_src   = (const float*)d_in[4];
    const float* w1_dst   = (const float*)d_in[5];
    const float* b1_dst   = (const float*)d_in[6];
    const float* w2_dst   = (const float*)d_in[7];
    const float* b2_dst   = (const float*)d_in[8];
    const float* b_hi     = (const float*)d_in[9];
    const float* a_hi     = (const float*)d_in[10];
    const float* b_lo     = (const float*)d_in[11];
    const float* a_lo     = (const float*)d_in[12];
    const float* u_eps    = (const float*)d_in[13];
    const int*   src      = (const int*)d_in[14];
    const int*   dst      = (const int*)d_in[15];
    const int*   idx_src_hi = (const int*)d_in[16];
    const int*   idx_src_lo = (const int*)d_in[17];
    const int*   idx_dst_hi = (const int*)d_in[18];
    const int*   idx_dst_lo = (const int*)d_in[19];
    float* out = (float*)d_out;

    k_imp<<<1, 32>>>(b_hi, a_hi, b_lo, a_lo);
    dim3 gfold(64, 4);
    k_fold<<<gfold, 256>>>(w1_src, w1_dst);
    k_gemm<<<2 * NB_BR, 256>>>(node_emb, b1_src, b1_dst, w2_src, w2_dst,
                               b2_src, b2_dst,
                               idx_src_lo, idx_src_hi, idx_dst_lo, idx_dst_hi);
    k_edge<<<NPART, 256>>>(src, dst, u_eps, out);
}